// round 9
// baseline (speedup 1.0000x reference)
#include <cuda_runtime.h>
#include <cuda_bf16.h>
#include <math.h>
#include <stdint.h>
#include <stddef.h>

#define NB 64
#define Hd 2048
#define G3 6144
#define TT 32
#define MELN 130
#define CHN 12
#define RHYN 3
#define K16N 128
#define FRAGU32 (4*K16N*32*8)
#define BPKSZ (768*K16N*32)
#define SST (K16N*32)

__device__ float g_h[2*NB*Hd];
__device__ float g_ha[2*NB*Hd];
__device__ float g_hb[2*NB*Hd];
__device__ float g_gic0[NB*G3];
__device__ float g_gi1z[NB*G3];
__device__ float g_gi1t[(size_t)TT*NB*G3];
__device__ float g_pA[4*NB*G3];
__device__ float g_pB[4*NB*G3];
__device__ float g_pC[4*NB*G3];
__device__ float g_rlo[TT*NB*RHYN];
__device__ int g_ridx[(TT+1)*NB];
__device__ int g_midx[(TT+1)*NB];
__device__ uint4 g_Bp0[BPKSZ], g_Bp1[BPKSZ], g_Bp2i[BPKSZ], g_Bp2h[BPKSZ];
__device__ uint32_t g_hfrag[2][FRAGU32], g_hafrag[2][FRAGU32], g_hbfrag[2][FRAGU32];

__device__ __forceinline__ float sigm_f(float x){ return 1.0f/(1.0f+expf(-x)); }
__device__ __forceinline__ float tanh_f(float x){ return 1.0f-2.0f/(expf(2.0f*x)+1.0f); }

__device__ __forceinline__ uint32_t packbf2(float x, float y){
    __nv_bfloat162 v = __floats2bfloat162_rn(x, y);
    return *reinterpret_cast<uint32_t*>(&v);
}
__device__ __forceinline__ void split2(float x, float y, uint32_t& hi, uint32_t& lo){
    __nv_bfloat16 hx = __float2bfloat16(x), hy = __float2bfloat16(y);
    float rx = x - __bfloat162float(hx);
    float ry = y - __bfloat162float(hy);
    __nv_bfloat162 H; H.x = hx; H.y = hy;
    hi = *reinterpret_cast<uint32_t*>(&H);
    lo = packbf2(rx, ry);
}

__device__ __forceinline__ void mma16816(float* d, uint32_t a0, uint32_t a1,
                                         uint32_t a2, uint32_t a3,
                                         uint32_t b0, uint32_t b1){
    asm volatile(
        "mma.sync.aligned.m16n8k16.row.col.f32.bf16.bf16.f32 "
        "{%0,%1,%2,%3}, {%4,%5,%6,%7}, {%8,%9}, {%0,%1,%2,%3};"
        : "+f"(d[0]), "+f"(d[1]), "+f"(d[2]), "+f"(d[3])
        : "r"(a0), "r"(a1), "r"(a2), "r"(a3), "r"(b0), "r"(b1));
}

// 18 MMAs, 6 accumulators, revisit distance 6. acc[s] pairs with b[s].
__device__ __forceinline__ void mma_step6(float acc[6][4], const uint4& ah,
                                          const uint4& al, const uint4 b[6]){
    mma16816(acc[0], ah.x,ah.y,ah.z,ah.w, b[0].x,b[0].y);
    mma16816(acc[2], ah.x,ah.y,ah.z,ah.w, b[2].x,b[2].y);
    mma16816(acc[4], ah.x,ah.y,ah.z,ah.w, b[4].x,b[4].y);
    mma16816(acc[1], ah.x,ah.y,ah.z,ah.w, b[1].x,b[1].y);
    mma16816(acc[3], ah.x,ah.y,ah.z,ah.w, b[3].x,b[3].y);
    mma16816(acc[5], ah.x,ah.y,ah.z,ah.w, b[5].x,b[5].y);
    mma16816(acc[0], ah.x,ah.y,ah.z,ah.w, b[0].z,b[0].w);
    mma16816(acc[2], ah.x,ah.y,ah.z,ah.w, b[2].z,b[2].w);
    mma16816(acc[4], ah.x,ah.y,ah.z,ah.w, b[4].z,b[4].w);
    mma16816(acc[1], ah.x,ah.y,ah.z,ah.w, b[1].z,b[1].w);
    mma16816(acc[3], ah.x,ah.y,ah.z,ah.w, b[3].z,b[3].w);
    mma16816(acc[5], ah.x,ah.y,ah.z,ah.w, b[5].z,b[5].w);
    mma16816(acc[0], al.x,al.y,al.z,al.w, b[0].x,b[0].y);
    mma16816(acc[2], al.x,al.y,al.z,al.w, b[2].x,b[2].y);
    mma16816(acc[4], al.x,al.y,al.z,al.w, b[4].x,b[4].y);
    mma16816(acc[1], al.x,al.y,al.z,al.w, b[1].x,b[1].y);
    mma16816(acc[3], al.x,al.y,al.z,al.w, b[3].x,b[3].y);
    mma16816(acc[5], al.x,al.y,al.z,al.w, b[5].x,b[5].y);
}

__global__ void k_init_idx(){
    int i = threadIdx.x;
    if (i < NB){ g_ridx[i] = RHYN-1; g_midx[i] = MELN-1; }
}

// matvec, b-tiled x8: grid (N/256, 8), block 256
__global__ void k_mv(const float* __restrict__ x, int K,
                     const float* __restrict__ W, int ldw, int off,
                     const float* __restrict__ bias, int N,
                     float* __restrict__ out, int act)
{
    __shared__ float xs[8*128];
    int b0 = blockIdx.y*8;
    for (int i = threadIdx.x; i < 8*K; i += 256)
        xs[i] = x[(b0 + i/K)*K + (i%K)];
    __syncthreads();
    int n = blockIdx.x*256 + threadIdx.x;
    float a[8];
#pragma unroll
    for (int j = 0; j < 8; j++) a[j] = 0.f;
    const float* wr = W + (size_t)n*ldw + off;
#pragma unroll 4
    for (int k = 0; k < K; k++){
        float w = wr[k];
#pragma unroll
        for (int j = 0; j < 8; j++) a[j] += xs[j*128 + k]*w;
    }
    float bb = bias[n];
#pragma unroll
    for (int j = 0; j < 8; j++){
        float v = a[j] + bb;
        if (act) v = tanh_f(v);
        out[(size_t)(b0 + j)*N + n] = v;
    }
}

__global__ void k_pack4(const float* __restrict__ W0, const float* __restrict__ W1,
                        const float* __restrict__ W2, const float* __restrict__ W3)
{
    const float* W; uint4* out;
    switch (blockIdx.y){
        case 0: W = W0; out = g_Bp0;  break;
        case 1: W = W1; out = g_Bp1;  break;
        case 2: W = W2; out = g_Bp2i; break;
        default: W = W3; out = g_Bp2h; break;
    }
    int id = blockIdx.x*256 + threadIdx.x;
    int l = id & 31, nt = id >> 12;
    int P = nt*8 + (l >> 2);
    int jt = P/48, rem = P%48, g = rem >> 4, c = rem & 15;
    int k16 = (id >> 5) & 127;
    const float* wr = W + (size_t)(g*Hd + jt*16 + c)*Hd + k16*16 + 2*(l&3);
    uint32_t h01, l01, h89, l89;
    split2(wr[0], wr[1], h01, l01);
    split2(wr[8], wr[9], h89, l89);
    out[id] = make_uint4(h01, h89, l01, l89);
}

__global__ void k_h2frag(const float* __restrict__ H, uint32_t* __restrict__ Af)
{
    int id = blockIdx.x*256 + threadIdx.x;
    int l = id & 31, k16 = (id >> 5) & 127, mt = id >> 12;
    int m0 = mt*16 + (l >> 2), k0 = k16*16 + 2*(l&3);
    const float* r0 = H + (size_t)m0*Hd + k0;
    const float* r1 = H + (size_t)(m0+8)*Hd + k0;
    uint32_t* o = Af + (size_t)id*8;
    uint32_t hi, lo;
    split2(r0[0], r0[1], hi, lo); o[0]=hi; o[4]=lo;
    split2(r1[0], r1[1], hi, lo); o[1]=hi; o[5]=lo;
    split2(r0[8], r0[9], hi, lo); o[2]=hi; o[6]=lo;
    split2(r1[8], r1[9], hi, lo); o[3]=hi; o[7]=lo;
}

// GEMM partials: blocks [0,128) use set A, [128,256) set B.
// block: jt4 = b>>2 (192 cols), ks = b&3 (512-K slice). 16 warps = 4mt x 4sg.
__global__ __launch_bounds__(512,1)
void k_gpart(const uint4* __restrict__ BpA, const uint32_t* __restrict__ AfA,
             float* __restrict__ outA,
             const uint4* __restrict__ BpB, const uint32_t* __restrict__ AfB,
             float* __restrict__ outB)
{
    int bid = blockIdx.x;
    const uint4* Bp = BpA; const uint32_t* Af = AfA; float* out = outA;
    if (bid >= 128){ Bp = BpB; Af = AfB; out = outB; bid -= 128; }
    int jt4 = bid >> 2, ks = bid & 3;
    int w = threadIdx.x >> 5, l = threadIdx.x & 31;
    int mt = w & 3, sg = w >> 2;
    int jt = jt4*4 + sg;

    float acc[6][4];
#pragma unroll
    for (int s = 0; s < 6; s++)
#pragma unroll
        for (int i = 0; i < 4; i++) acc[s][i] = 0.f;

    const uint4* bptr = Bp + ((size_t)(jt*6)*K16N + ks*32)*32 + l;
    const uint4* ap = (const uint4*)(Af + (((size_t)mt*K16N + ks*32)*32 + l)*8);

    uint4 A0h = ap[0], A0l = ap[1], A1h = ap[64], A1l = ap[65];
    uint4 B0[6], B1[6];
#pragma unroll
    for (int s = 0; s < 6; s++){
        B0[s] = __ldg(bptr + (size_t)s*SST);
        B1[s] = __ldg(bptr + (size_t)s*SST + 32);
    }
#pragma unroll 1
    for (int k = 0; k < 30; k += 2){
        mma_step6(acc, A0h, A0l, B0);
        ap += 128; bptr += 64;
        A0h = ap[0]; A0l = ap[1];
#pragma unroll
        for (int s = 0; s < 6; s++) B0[s] = __ldg(bptr + (size_t)s*SST);
        mma_step6(acc, A1h, A1l, B1);
        A1h = ap[64]; A1l = ap[65];
#pragma unroll
        for (int s = 0; s < 6; s++) B1[s] = __ldg(bptr + (size_t)s*SST + 32);
    }
    mma_step6(acc, A0h, A0l, B0);
    mma_step6(acc, A1h, A1l, B1);

    int q = l >> 2, tp = l & 3, m0 = mt*16 + q, m1 = m0 + 8;
#pragma unroll
    for (int s = 0; s < 6; s++){
        int g = s >> 1, col = jt*16 + (s&1)*8 + 2*tp;
        *(float2*)&out[((size_t)(ks*NB + m0))*G3 + g*Hd + col] =
            make_float2(acc[s][0], acc[s][1]);
        *(float2*)&out[((size_t)(ks*NB + m1))*G3 + g*Hd + col] =
            make_float2(acc[s][2], acc[s][3]);
    }
}

// combine: sum 4 k-partials, GRU epilogue, write h (fp32) + frag. grid 128 x 512.
__global__ void k_comb(const float* __restrict__ pA, const float* __restrict__ bA,
                       const float* __restrict__ pB, const float* __restrict__ bB,
                       const float* __restrict__ gip,
                       const float* __restrict__ Woh, int ldw,
                       const int* __restrict__ idx,
                       const float* __restrict__ Hfp, float* __restrict__ outH,
                       uint32_t* __restrict__ Frag)
{
    int i = blockIdx.x*512 + threadIdx.x;
    int b = i >> 10, up = i & 1023, u0 = 2*up;
    int ix = Woh ? idx[b] : 0;
    float hv[2];
#pragma unroll
    for (int e = 0; e < 2; e++){
        int u = u0 + e;
        float ghr = bA[u], ghz = bA[Hd+u], ghn = bA[2*Hd+u];
#pragma unroll
        for (int ks = 0; ks < 4; ks++){
            const float* p = pA + ((size_t)(ks*NB + b))*G3 + u;
            ghr += p[0]; ghz += p[Hd]; ghn += p[2*Hd];
        }
        float gir, giz, gin;
        if (pB){
            gir = bB[u]; giz = bB[Hd+u]; gin = bB[2*Hd+u];
#pragma unroll
            for (int ks = 0; ks < 4; ks++){
                const float* p = pB + ((size_t)(ks*NB + b))*G3 + u;
                gir += p[0]; giz += p[Hd]; gin += p[2*Hd];
            }
        } else {
            gir = gip[(size_t)b*G3 + u];
            giz = gip[(size_t)b*G3 + Hd + u];
            gin = gip[(size_t)b*G3 + 2*Hd + u];
            if (Woh){
                gir += Woh[(size_t)u*ldw + ix];
                giz += Woh[(size_t)(Hd+u)*ldw + ix];
                gin += Woh[(size_t)(2*Hd+u)*ldw + ix];
            }
        }
        float r = sigm_f(gir + ghr);
        float uu = sigm_f(giz + ghz);
        float n = tanh_f(gin + r*ghn);
        hv[e] = (1.f - uu)*n + uu*Hfp[(size_t)b*Hd + u];
    }
    *(float2*)&outH[(size_t)b*Hd + u0] = make_float2(hv[0], hv[1]);
    uint32_t hi, lo; split2(hv[0], hv[1], hi, lo);
    int mt = b >> 4, rw = b & 15, q = rw & 7, rs = rw >> 3;
    int k16 = u0 >> 4, kk = u0 & 15, tp = (kk & 7) >> 1;
    int r = ((kk >= 8) ? 2 : 0) + rs;
    uint32_t* fb = Frag + (((size_t)mt*K16N + k16)*32 + q*4 + tp)*8;
    fb[r] = hi; fb[r+4] = lo;
}

__global__ void k_rhylog(const float* __restrict__ Hn, const float* __restrict__ wo0,
                         const float* __restrict__ bo0,
                         float* __restrict__ rlo, int* __restrict__ ridx)
{
    int b = blockIdx.x, tid = threadIdx.x;
    float p0=0.f, p1=0.f, p2=0.f;
    for (int k = tid; k < Hd; k += 128){
        float h = Hn[(size_t)b*Hd + k];
        p0 += h*wo0[k]; p1 += h*wo0[Hd+k]; p2 += h*wo0[2*Hd+k];
    }
    __shared__ float s0[128], s1[128], s2[128];
    s0[tid]=p0; s1[tid]=p1; s2[tid]=p2;
    __syncthreads();
    for (int off = 64; off > 0; off >>= 1){
        if (tid < off){ s0[tid]+=s0[tid+off]; s1[tid]+=s1[tid+off]; s2[tid]+=s2[tid+off]; }
        __syncthreads();
    }
    if (tid == 0){
        float l0 = s0[0]+bo0[0], l1 = s1[0]+bo0[1], l2 = s2[0]+bo0[2];
        float m = fmaxf(l0, fmaxf(l1, l2));
        float z = m + logf(expf(l0-m)+expf(l1-m)+expf(l2-m));
        rlo[b*3+0]=l0-z; rlo[b*3+1]=l1-z; rlo[b*3+2]=l2-z;
        int ix = 0; float bv = l0;
        if (l1 > bv){ bv = l1; ix = 1; }
        if (l2 > bv){ bv = l2; ix = 2; }
        ridx[b] = ix;
    }
}

__global__ void k_gi1t(const float* __restrict__ gi1z, const float* __restrict__ cond,
                       const float* __restrict__ rlo, const float* __restrict__ w_ih1,
                       float* __restrict__ gi1t)
{
    int n = blockIdx.x*256 + threadIdx.x;
    int t = blockIdx.y;
    float wr[RHYN], wc[CHN];
#pragma unroll
    for (int j = 0; j < RHYN; j++) wr[j] = w_ih1[(size_t)n*273 + MELN + j];
#pragma unroll
    for (int j = 0; j < CHN; j++) wc[j] = w_ih1[(size_t)n*273 + MELN + RHYN + 128 + j];
    for (int b = 0; b < NB; b++){
        float s = gi1z[(size_t)b*G3 + n];
        const float* r = &rlo[(t*NB + b)*RHYN];
        s += r[0]*wr[0] + r[1]*wr[1] + r[2]*wr[2];
        const float* c = &cond[(b*TT + t)*CHN];
#pragma unroll
        for (int j = 0; j < CHN; j++) s += c[j]*wc[j];
        gi1t[((size_t)t*NB + b)*G3 + n] = s;
    }
}

__global__ void k_mellog(const float* __restrict__ Hn, const float* __restrict__ wo1,
                         const float* __restrict__ bo1,
                         float* __restrict__ outmel, int t, int* __restrict__ midx)
{
    __shared__ __align__(16) float hs[Hd];
    __shared__ float ls[MELN];
    __shared__ float red[256];
    int b = blockIdx.x, tid = threadIdx.x;
    int w = tid >> 5, l = tid & 31;
    for (int k = tid; k < Hd; k += 256) hs[k] = Hn[(size_t)b*Hd + k];
    __syncthreads();
    const float4* h4 = (const float4*)hs;
    for (int r = w; r < MELN; r += 8){
        const float4* w4 = (const float4*)(wo1 + (size_t)r*Hd);
        float s = 0.f;
        for (int c = l; c < Hd/4; c += 32){
            float4 a = h4[c], q = w4[c];
            s += a.x*q.x + a.y*q.y + a.z*q.z + a.w*q.w;
        }
#pragma unroll
        for (int off = 16; off > 0; off >>= 1) s += __shfl_xor_sync(0xffffffffu, s, off);
        if (l == 0) ls[r] = s + bo1[r];
    }
    __syncthreads();
    red[tid] = (tid < MELN) ? ls[tid] : -3.4e38f;
    __syncthreads();
    for (int off = 128; off > 0; off >>= 1){
        if (tid < off) red[tid] = fmaxf(red[tid], red[tid+off]);
        __syncthreads();
    }
    float m = red[0];
    __syncthreads();
    red[tid] = (tid < MELN) ? expf(ls[tid]-m) : 0.f;
    __syncthreads();
    for (int off = 128; off > 0; off >>= 1){
        if (tid < off) red[tid] += red[tid+off];
        __syncthreads();
    }
    float z = m + logf(red[0]);
    if (tid < MELN)
        outmel[((size_t)b*TT + t)*MELN + tid] = ls[tid] - z;
    if (tid == 0){
        int ix = 0; float bv = ls[0];
        for (int c = 1; c < MELN; c++) if (ls[c] > bv){ bv = ls[c]; ix = c; }
        midx[b] = ix;
    }
}

extern "C" void kernel_launch(void* const* d_in, const int* in_sizes, int n_in,
                              void* d_out, int out_size)
{
    const float* z1    = (const float*)d_in[0];
    const float* z2    = (const float*)d_in[1];
    const float* cond  = (const float*)d_in[2];
    const float* w_ih0 = (const float*)d_in[3];
    const float* w_hh0 = (const float*)d_in[4];
    const float* b_ih0 = (const float*)d_in[5];
    const float* b_hh0 = (const float*)d_in[6];
    const float* w_ih1 = (const float*)d_in[7];
    const float* w_hh1 = (const float*)d_in[8];
    const float* b_ih1 = (const float*)d_in[9];
    const float* b_hh1 = (const float*)d_in[10];
    const float* w_ih2 = (const float*)d_in[11];
    const float* w_hh2 = (const float*)d_in[12];
    const float* b_ih2 = (const float*)d_in[13];
    const float* b_hh2 = (const float*)d_in[14];
    const float* wi0   = (const float*)d_in[15];
    const float* bi0   = (const float*)d_in[16];
    const float* wo0   = (const float*)d_in[17];
    const float* bo0   = (const float*)d_in[18];
    const float* wi1   = (const float*)d_in[19];
    const float* bi1   = (const float*)d_in[20];
    const float* wo1   = (const float*)d_in[21];
    const float* bo1   = (const float*)d_in[22];
    float* out = (float*)d_out;

    float *hB,*haB,*hbB,*gic0,*gi1z,*gi1t,*pA,*pB,*pC,*rlo;
    int *ridx,*midx;
    uint4 *Bp0,*Bp1,*Bp2i,*Bp2h;
    uint32_t *hfr,*hafr,*hbfr;
    cudaGetSymbolAddress((void**)&hB, g_h);
    cudaGetSymbolAddress((void**)&haB, g_ha);
    cudaGetSymbolAddress((void**)&hbB, g_hb);
    cudaGetSymbolAddress((void**)&gic0, g_gic0);
    cudaGetSymbolAddress((void**)&gi1z, g_gi1z);
    cudaGetSymbolAddress((void**)&gi1t, g_gi1t);
    cudaGetSymbolAddress((void**)&pA, g_pA);
    cudaGetSymbolAddress((void**)&pB, g_pB);
    cudaGetSymbolAddress((void**)&pC, g_pC);
    cudaGetSymbolAddress((void**)&rlo, g_rlo);
    cudaGetSymbolAddress((void**)&ridx, g_ridx);
    cudaGetSymbolAddress((void**)&midx, g_midx);
    cudaGetSymbolAddress((void**)&Bp0, g_Bp0);
    cudaGetSymbolAddress((void**)&Bp1, g_Bp1);
    cudaGetSymbolAddress((void**)&Bp2i, g_Bp2i);
    cudaGetSymbolAddress((void**)&Bp2h, g_Bp2h);
    cudaGetSymbolAddress((void**)&hfr, g_hfrag);
    cudaGetSymbolAddress((void**)&hafr, g_hafrag);
    cudaGetSymbolAddress((void**)&hbfr, g_hbfrag);

    float* hbuf[2]  = { hB,  hB  + NB*Hd };
    float* habuf[2] = { haB, haB + NB*Hd };
    float* hbbuf[2] = { hbB, hbB + NB*Hd };
    uint32_t* hfrag[2]  = { hfr,  hfr  + FRAGU32 };
    uint32_t* hafrag[2] = { hafr, hafr + FRAGU32 };
    uint32_t* hbfrag[2] = { hbfr, hbfr + FRAGU32 };

    k_init_idx<<<1, 64>>>();
    k_pack4<<<dim3(BPKSZ/256, 4), 256>>>(w_hh0, w_hh1, w_ih2, w_hh2);

    k_mv<<<dim3(Hd/256, 8), 256>>>(z2, 128, wi0, 128, 0, bi0, Hd, hbuf[0], 1);
    k_mv<<<dim3(Hd/256, 8), 256>>>(z1, 128, wi1, 128, 0, bi1, Hd, habuf[0], 1);
    k_mv<<<dim3(G3/256, 8), 256>>>(z2, 128, w_ih0, 131, RHYN, b_ih0, G3, gic0, 0);
    k_mv<<<dim3(G3/256, 8), 256>>>(z1, 128, w_ih1, 273, MELN+RHYN, b_ih1, G3, gi1z, 0);
    k_h2frag<<<64, 256>>>(hbuf[0], hfrag[0]);
    k_h2frag<<<64, 256>>>(habuf[0], hafrag[0]);

    // ---- rhythm phase ----
    for (int t = 0; t < TT; t++){
        int nt = (t+1) & 1;
        k_gpart<<<128, 512>>>(Bp0, hfrag[t&1], pA, 0, 0, 0);
        k_comb<<<128, 512>>>(pA, b_hh0, 0, 0, gic0, w_ih0, 131, ridx + t*NB,
                             hbuf[t&1], hbuf[nt], hfrag[nt]);
        k_rhylog<<<NB, 128>>>(hbuf[nt], wo0, bo0, rlo + t*NB*RHYN, ridx + (t+1)*NB);
    }

    k_gi1t<<<dim3(G3/256, TT), 256>>>(gi1z, cond, rlo, w_ih1, gi1t);

    // ---- melody phase ----
    for (int t = 0; t < TT; t++){
        int nt = (t+1) & 1;
        if (t == 0){
            k_gpart<<<128, 512>>>(Bp1, hafrag[0], pA, 0, 0, 0);
            k_comb<<<128, 512>>>(pA, b_hh1, 0, 0, gi1t, w_ih1, 273, midx,
                                 habuf[0], habuf[1], hafrag[1]);
            // gi2 (from ha') + gh2 (from ha' too, since hb_0 := ha')
            k_gpart<<<256, 512>>>(Bp2i, hafrag[1], pC, Bp2h, hafrag[1], pB);
            k_comb<<<128, 512>>>(pB, b_hh2, pC, b_ih2, 0, 0, 0, 0,
                                 habuf[1], hbbuf[1], hbfrag[1]);
        } else {
            // GRU1 gh partials + GRU2 gh partials (independent) in one launch
            k_gpart<<<256, 512>>>(Bp1, hafrag[t&1], pA, Bp2h, hbfrag[t&1], pB);
            k_comb<<<128, 512>>>(pA, b_hh1, 0, 0, gi1t + (size_t)t*NB*G3,
                                 w_ih1, 273, midx + t*NB,
                                 habuf[t&1], habuf[nt], hafrag[nt]);
            k_gpart<<<128, 512>>>(Bp2i, hafrag[nt], pC, 0, 0, 0);
            k_comb<<<128, 512>>>(pB, b_hh2, pC, b_ih2, 0, 0, 0, 0,
                                 hbbuf[t&1], hbbuf[nt], hbfrag[nt]);
        }
        k_mellog<<<NB, 256>>>(hbbuf[(t+1)&1], wo1, bo1, out, t, midx + (t+1)*NB);
    }
}

// round 11
// speedup vs baseline: 1.2664x; 1.2664x over previous
#include <cuda_runtime.h>
#include <cuda_bf16.h>
#include <math.h>
#include <stdint.h>
#include <stddef.h>

#define NB 64
#define Hd 2048
#define G3 6144
#define TT 32
#define MELN 130
#define CHN 12
#define RHYN 3
#define K16N 128
#define NBHd (NB*Hd)
#define FRAGU32 (4*K16N*32*8)
#define BPKSZ (768*K16N*32)
#define SST (K16N*32)

// ---------------- device globals -------------------------------------------------
__device__ float g_h[2*NBHd];
__device__ float g_ha[2*NBHd];
__device__ float g_hb[2*NBHd];
__device__ float g_gic0[NB*G3];
__device__ float g_gi1z[NB*G3];
__device__ float g_gi1t[(size_t)TT*NB*G3];
__device__ float g_rlo[TT*NB*RHYN];
__device__ int g_ridx[(TT+1)*NB];
__device__ int g_midx[(TT+1)*NB];
__device__ int g_bar;
__device__ uint4 g_Bp0[BPKSZ], g_Bp1[BPKSZ], g_Bp2i[BPKSZ], g_Bp2h[BPKSZ];
__device__ uint32_t g_hfrag[2][FRAGU32], g_hafrag[2][FRAGU32], g_hbfrag[2][FRAGU32];

// ---------------- helpers ---------------------------------------------------------
__device__ __forceinline__ float sigm_f(float x){ return 1.0f/(1.0f+expf(-x)); }
__device__ __forceinline__ float tanh_f(float x){ return 1.0f-2.0f/(expf(2.0f*x)+1.0f); }

__device__ __forceinline__ uint32_t packbf2(float x, float y){
    __nv_bfloat162 v = __floats2bfloat162_rn(x, y);
    return *reinterpret_cast<uint32_t*>(&v);
}
__device__ __forceinline__ void split2(float x, float y, uint32_t& hi, uint32_t& lo){
    __nv_bfloat16 hx = __float2bfloat16(x), hy = __float2bfloat16(y);
    float rx = x - __bfloat162float(hx);
    float ry = y - __bfloat162float(hy);
    __nv_bfloat162 H; H.x = hx; H.y = hy;
    hi = *reinterpret_cast<uint32_t*>(&H);
    lo = packbf2(rx, ry);
}

__device__ __forceinline__ void mma16816(float* d, uint32_t a0, uint32_t a1,
                                         uint32_t a2, uint32_t a3,
                                         uint32_t b0, uint32_t b1){
    asm volatile(
        "mma.sync.aligned.m16n8k16.row.col.f32.bf16.bf16.f32 "
        "{%0,%1,%2,%3}, {%4,%5,%6,%7}, {%8,%9}, {%0,%1,%2,%3};"
        : "+f"(d[0]), "+f"(d[1]), "+f"(d[2]), "+f"(d[3])
        : "r"(a0), "r"(a1), "r"(a2), "r"(a3), "r"(b0), "r"(b1));
}

__device__ __forceinline__ void mma_step6(float acc[2][3][4], const uint4& ah,
                                          const uint4& al, const uint4 b[6]){
    mma16816(acc[0][0], ah.x,ah.y,ah.z,ah.w, b[0].x,b[0].y);
    mma16816(acc[0][1], ah.x,ah.y,ah.z,ah.w, b[2].x,b[2].y);
    mma16816(acc[0][2], ah.x,ah.y,ah.z,ah.w, b[4].x,b[4].y);
    mma16816(acc[1][0], ah.x,ah.y,ah.z,ah.w, b[1].x,b[1].y);
    mma16816(acc[1][1], ah.x,ah.y,ah.z,ah.w, b[3].x,b[3].y);
    mma16816(acc[1][2], ah.x,ah.y,ah.z,ah.w, b[5].x,b[5].y);
    mma16816(acc[0][0], ah.x,ah.y,ah.z,ah.w, b[0].z,b[0].w);
    mma16816(acc[0][1], ah.x,ah.y,ah.z,ah.w, b[2].z,b[2].w);
    mma16816(acc[0][2], ah.x,ah.y,ah.z,ah.w, b[4].z,b[4].w);
    mma16816(acc[1][0], ah.x,ah.y,ah.z,ah.w, b[1].z,b[1].w);
    mma16816(acc[1][1], ah.x,ah.y,ah.z,ah.w, b[3].z,b[3].w);
    mma16816(acc[1][2], ah.x,ah.y,ah.z,ah.w, b[5].z,b[5].w);
    mma16816(acc[0][0], al.x,al.y,al.z,al.w, b[0].x,b[0].y);
    mma16816(acc[0][1], al.x,al.y,al.z,al.w, b[2].x,b[2].y);
    mma16816(acc[0][2], al.x,al.y,al.z,al.w, b[4].x,b[4].y);
    mma16816(acc[1][0], al.x,al.y,al.z,al.w, b[1].x,b[1].y);
    mma16816(acc[1][1], al.x,al.y,al.z,al.w, b[3].x,b[3].y);
    mma16816(acc[1][2], al.x,al.y,al.z,al.w, b[5].x,b[5].y);
}

// grid barrier: all 128 co-resident blocks
__device__ __forceinline__ void gbar(int& tgt){
    __threadfence();
    __syncthreads();
    if (threadIdx.x == 0){
        tgt += 128;
        atomicAdd(&g_bar, 1);
        int v;
        do {
            asm volatile("ld.acquire.gpu.global.b32 %0, [%1];" : "=r"(v) : "l"(&g_bar));
        } while (v < tgt);
    }
    __syncthreads();
}

// ---------------- pre-kernels -----------------------------------------------------
__global__ void k_init(){
    int i = threadIdx.x;
    if (i == 0) g_bar = 0;
    if (i < NB){ g_ridx[i] = RHYN-1; g_midx[i] = MELN-1; }
}

__global__ void k_mv(const float* __restrict__ x, int K,
                     const float* __restrict__ W, int ldw, int off,
                     const float* __restrict__ bias, int N,
                     float* __restrict__ out, int act)
{
    __shared__ float xs[8*128];
    int b0 = blockIdx.y*8;
    for (int i = threadIdx.x; i < 8*K; i += 256)
        xs[i] = x[(b0 + i/K)*K + (i%K)];
    __syncthreads();
    int n = blockIdx.x*256 + threadIdx.x;
    float a[8];
#pragma unroll
    for (int j = 0; j < 8; j++) a[j] = 0.f;
    const float* wr = W + (size_t)n*ldw + off;
#pragma unroll 4
    for (int k = 0; k < K; k++){
        float w = wr[k];
#pragma unroll
        for (int j = 0; j < 8; j++) a[j] += xs[j*128 + k]*w;
    }
    float bb = bias[n];
#pragma unroll
    for (int j = 0; j < 8; j++){
        float v = a[j] + bb;
        if (act) v = tanh_f(v);
        out[(size_t)(b0 + j)*N + n] = v;
    }
}

__global__ void k_pack4(const float* __restrict__ W0, const float* __restrict__ W1,
                        const float* __restrict__ W2, const float* __restrict__ W3)
{
    const float* W; uint4* out;
    switch (blockIdx.y){
        case 0: W = W0; out = g_Bp0;  break;
        case 1: W = W1; out = g_Bp1;  break;
        case 2: W = W2; out = g_Bp2i; break;
        default: W = W3; out = g_Bp2h; break;
    }
    int id = blockIdx.x*256 + threadIdx.x;
    int l = id & 31, nt = id >> 12;
    int P = nt*8 + (l >> 2);
    int jt = P/48, rem = P%48, g = rem >> 4, c = rem & 15;
    int k16 = (id >> 5) & 127;
    const float* wr = W + (size_t)(g*Hd + jt*16 + c)*Hd + k16*16 + 2*(l&3);
    uint32_t h01, l01, h89, l89;
    split2(wr[0], wr[1], h01, l01);
    split2(wr[8], wr[9], h89, l89);
    out[id] = make_uint4(h01, h89, l01, l89);
}

__global__ void k_h2frag(const float* __restrict__ H, uint32_t* __restrict__ Af)
{
    int id = blockIdx.x*256 + threadIdx.x;
    int l = id & 31, k16 = (id >> 5) & 127, mt = id >> 12;
    int m0 = mt*16 + (l >> 2), k0 = k16*16 + 2*(l&3);
    const float* r0 = H + (size_t)m0*Hd + k0;
    const float* r1 = H + (size_t)(m0+8)*Hd + k0;
    uint32_t* o = Af + (size_t)id*8;
    uint32_t hi, lo;
    split2(r0[0], r0[1], hi, lo); o[0]=hi; o[4]=lo;
    split2(r1[0], r1[1], hi, lo); o[1]=hi; o[5]=lo;
    split2(r0[8], r0[9], hi, lo); o[2]=hi; o[6]=lo;
    split2(r1[8], r1[9], hi, lo); o[3]=hi; o[7]=lo;
}

// ---------------- persistent-kernel device bodies ---------------------------------
// full-K GEMM tile: block jt, 16 warps = 4mt x 4kh. threads<128 end with valid acc.
__device__ __forceinline__ void gemm_acc(const uint4* __restrict__ Bpk,
                                         const uint32_t* __restrict__ Af,
                                         float acc[2][3][4], float* sred)
{
    __syncthreads();   // protect sred reuse
    int tid = threadIdx.x, jt = blockIdx.x;
    int w = tid >> 5, l = tid & 31;
    int mt = w & 3, kh = w >> 2;
#pragma unroll
    for (int n = 0; n < 2; n++)
#pragma unroll
        for (int g = 0; g < 3; g++)
#pragma unroll
            for (int i = 0; i < 4; i++) acc[n][g][i] = 0.f;

    const uint4* bptr = Bpk + ((size_t)(jt*6)*K16N + kh*32)*32 + l;
    const uint4* ap4 = (const uint4*)(Af + (((size_t)mt*K16N + kh*32)*32 + l)*8);

    uint4 A0h = __ldcg(ap4), A0l = __ldcg(ap4+1);
    uint4 A1h = __ldcg(ap4+64), A1l = __ldcg(ap4+65);
    uint4 B0[6], B1[6];
#pragma unroll
    for (int s = 0; s < 6; s++){
        B0[s] = __ldg(bptr + (size_t)s*SST);
        B1[s] = __ldg(bptr + (size_t)s*SST + 32);
    }
#pragma unroll 1
    for (int k16 = 0; k16 < 30; k16 += 2){
        mma_step6(acc, A0h, A0l, B0);
        ap4 += 128; bptr += 64;
        A0h = __ldcg(ap4); A0l = __ldcg(ap4+1);
#pragma unroll
        for (int s = 0; s < 6; s++) B0[s] = __ldg(bptr + (size_t)s*SST);
        mma_step6(acc, A1h, A1l, B1);
        A1h = __ldcg(ap4+64); A1l = __ldcg(ap4+65);
#pragma unroll
        for (int s = 0; s < 6; s++) B1[s] = __ldg(bptr + (size_t)s*SST + 32);
    }
    mma_step6(acc, A0h, A0l, B0);
    mma_step6(acc, A1h, A1l, B1);

    if (kh){
#pragma unroll
        for (int n = 0; n < 2; n++)
#pragma unroll
            for (int g = 0; g < 3; g++)
#pragma unroll
                for (int i = 0; i < 4; i++)
                    sred[(((kh-1)*4 + mt)*32 + l)*24 + (n*3+g)*4 + i] = acc[n][g][i];
    }
    __syncthreads();
    if (!kh){
#pragma unroll
        for (int s = 0; s < 3; s++)
#pragma unroll
            for (int n = 0; n < 2; n++)
#pragma unroll
                for (int g = 0; g < 3; g++)
#pragma unroll
                    for (int i = 0; i < 4; i++)
                        acc[n][g][i] += sred[((s*4 + mt)*32 + l)*24 + (n*3+g)*4 + i];
    }
}

// GRU epilogue, gi from buffer + one-hot column. call with tid<128 only.
__device__ __forceinline__ void epiA(const float acc[2][3][4],
    const float* __restrict__ bias, const float* __restrict__ gi,
    const float* __restrict__ Woh, int ldw, const int* __restrict__ idx,
    const float* __restrict__ Hfp, float* __restrict__ outH,
    uint32_t* __restrict__ Frag)
{
    int tid = threadIdx.x, jt = blockIdx.x;
    int mt = tid >> 5, l = tid & 31;
    int q = l >> 2, tp = l & 3;
    int m0 = mt*16 + q, m1 = m0 + 8;
    int ix0 = __ldcg(idx + m0), ix1 = __ldcg(idx + m1);
    int lp = q*4 + tp;
    uint32_t* fb = Frag + (((size_t)mt*K16N + jt)*32 + lp)*8;
#pragma unroll
    for (int nh = 0; nh < 2; nh++){
        int c0 = jt*16 + nh*8 + 2*tp, c1 = c0 + 1;
        float br = __ldg(bias+c0), brX = __ldg(bias+c1);
        float bz = __ldg(bias+Hd+c0), bzX = __ldg(bias+Hd+c1);
        float bn = __ldg(bias+2*Hd+c0), bnX = __ldg(bias+2*Hd+c1);
        float hout[4];
#pragma unroll
        for (int v = 0; v < 4; v++){
            int b = (v & 2) ? m1 : m0;
            int c = (v & 1) ? c1 : c0;
            int ix = (v & 2) ? ix1 : ix0;
            float gir = __ldcg(gi + (size_t)b*G3 + c) + __ldg(Woh + (size_t)c*ldw + ix);
            float giz = __ldcg(gi + (size_t)b*G3 + Hd + c) + __ldg(Woh + (size_t)(Hd+c)*ldw + ix);
            float gin = __ldcg(gi + (size_t)b*G3 + 2*Hd + c) + __ldg(Woh + (size_t)(2*Hd+c)*ldw + ix);
            float ghr = acc[nh][0][v] + ((v & 1) ? brX : br);
            float ghz = acc[nh][1][v] + ((v & 1) ? bzX : bz);
            float ghn = acc[nh][2][v] + ((v & 1) ? bnX : bn);
            float r = sigm_f(gir + ghr);
            float u = sigm_f(giz + ghz);
            float n = tanh_f(gin + r*ghn);
            float hp = __ldcg(Hfp + (size_t)b*Hd + c);
            hout[v] = (1.f - u)*n + u*hp;
            outH[(size_t)b*Hd + c] = hout[v];
        }
        uint32_t hi0, lo0, hi1, lo1;
        split2(hout[0], hout[1], hi0, lo0);
        split2(hout[2], hout[3], hi1, lo1);
        fb[nh*2 + 0] = hi0; fb[nh*2 + 1] = hi1;
        fb[4 + nh*2 + 0] = lo0; fb[4 + nh*2 + 1] = lo1;
    }
}

// GRU2 epilogue: gi from acc (raw), gh from gh2 (raw). tid<128 only.
__device__ __forceinline__ void epi2(const float acc[2][3][4], const float gh2[2][3][4],
    const float* __restrict__ bi, const float* __restrict__ bh,
    const float* __restrict__ Hfp, float* __restrict__ outH,
    uint32_t* __restrict__ Frag)
{
    int tid = threadIdx.x, jt = blockIdx.x;
    int mt = tid >> 5, l = tid & 31;
    int q = l >> 2, tp = l & 3;
    int m0 = mt*16 + q, m1 = m0 + 8;
    int lp = q*4 + tp;
    uint32_t* fb = Frag + (((size_t)mt*K16N + jt)*32 + lp)*8;
#pragma unroll
    for (int nh = 0; nh < 2; nh++){
        int c0 = jt*16 + nh*8 + 2*tp, c1 = c0 + 1;
        float hout[4];
#pragma unroll
        for (int v = 0; v < 4; v++){
            int b = (v & 2) ? m1 : m0;
            int c = (v & 1) ? c1 : c0;
            float gir = acc[nh][0][v] + __ldg(bi + c);
            float giz = acc[nh][1][v] + __ldg(bi + Hd + c);
            float gin = acc[nh][2][v] + __ldg(bi + 2*Hd + c);
            float ghr = gh2[nh][0][v] + __ldg(bh + c);
            float ghz = gh2[nh][1][v] + __ldg(bh + Hd + c);
            float ghn = gh2[nh][2][v] + __ldg(bh + 2*Hd + c);
            float r = sigm_f(gir + ghr);
            float u = sigm_f(giz + ghz);
            float n = tanh_f(gin + r*ghn);
            float hp = __ldcg(Hfp + (size_t)b*Hd + c);
            hout[v] = (1.f - u)*n + u*hp;
            outH[(size_t)b*Hd + c] = hout[v];
        }
        uint32_t hi0, lo0, hi1, lo1;
        split2(hout[0], hout[1], hi0, lo0);
        split2(hout[2], hout[3], hi1, lo1);
        fb[nh*2 + 0] = hi0; fb[nh*2 + 1] = hi1;
        fb[4 + nh*2 + 0] = lo0; fb[4 + nh*2 + 1] = lo1;
    }
}

// rhythm logits: blocks < 64, 384 active threads
__device__ __forceinline__ void rhy_body(const float* __restrict__ Hn,
    const float* __restrict__ wo0, const float* __restrict__ bo0,
    float* __restrict__ rlo, int* __restrict__ ridx, float* sm)
{
    int b = blockIdx.x, tid = threadIdx.x;
    if (tid < 384){
        int g = tid >> 7, s = tid & 127;
        float p = 0.f;
        for (int k = s; k < Hd; k += 128)
            p += __ldcg(Hn + (size_t)b*Hd + k) * __ldg(wo0 + (size_t)g*Hd + k);
        sm[tid] = p;
    }
    __syncthreads();
    for (int off = 64; off > 0; off >>= 1){
        if (tid < 384 && (tid & 127) < off) sm[tid] += sm[tid + off];
        __syncthreads();
    }
    if (tid == 0){
        float l0 = sm[0] + __ldg(bo0+0), l1 = sm[128] + __ldg(bo0+1), l2 = sm[256] + __ldg(bo0+2);
        float m = fmaxf(l0, fmaxf(l1, l2));
        float z = m + logf(expf(l0-m) + expf(l1-m) + expf(l2-m));
        rlo[b*3+0] = l0 - z; rlo[b*3+1] = l1 - z; rlo[b*3+2] = l2 - z;
        int ix = 0; float bv = l0;
        if (l1 > bv){ bv = l1; ix = 1; }
        if (l2 > bv){ bv = l2; ix = 2; }
        ridx[b] = ix;
    }
}

// melody logits: blocks < 64, all 512 threads
__device__ __forceinline__ void mel_body(const float* __restrict__ Hn,
    const float* __restrict__ wo1, const float* __restrict__ bo1,
    float* __restrict__ outmel, int t, int* __restrict__ midx, float* sm)
{
    float* hs = sm;            // 2048
    float* ls = sm + 2048;     // 160
    float* red = sm + 2208;    // 512
    int b = blockIdx.x, tid = threadIdx.x;
    for (int k = tid; k < Hd; k += 512) hs[k] = __ldcg(Hn + (size_t)b*Hd + k);
    __syncthreads();
    int w = tid >> 5, l = tid & 31;
    const float4* h4 = (const float4*)hs;
    for (int r = w; r < MELN; r += 16){
        const float4* w4 = (const float4*)(wo1 + (size_t)r*Hd);
        float s = 0.f;
        for (int c = l; c < Hd/4; c += 32){
            float4 a = h4[c], q = __ldg(w4 + c);
            s += a.x*q.x + a.y*q.y + a.z*q.z + a.w*q.w;
        }
#pragma unroll
        for (int off = 16; off > 0; off >>= 1) s += __shfl_xor_sync(0xffffffffu, s, off);
        if (l == 0) ls[r] = s + __ldg(bo1 + r);
    }
    __syncthreads();
    red[tid] = (tid < MELN) ? ls[tid] : -3.4e38f;
    __syncthreads();
    for (int off = 256; off > 0; off >>= 1){
        if (tid < off) red[tid] = fmaxf(red[tid], red[tid + off]);
        __syncthreads();
    }
    float m = red[0];
    __syncthreads();
    red[tid] = (tid < MELN) ? expf(ls[tid] - m) : 0.f;
    __syncthreads();
    for (int off = 256; off > 0; off >>= 1){
        if (tid < off) red[tid] += red[tid + off];
        __syncthreads();
    }
    float z = m + logf(red[0]);
    if (tid < MELN)
        outmel[((size_t)b*TT + t)*MELN + tid] = ls[tid] - z;
    if (tid == 0){
        int ix = 0; float bv = ls[0];
        for (int c = 1; c < MELN; c++) if (ls[c] > bv){ bv = ls[c]; ix = c; }
        midx[b] = ix;
    }
    __syncthreads();
}

// gi1t builder: 128 blocks x 512 threads cover all (t,n)
__device__ __forceinline__ void gi1t_body(const float* __restrict__ cond,
                                          const float* __restrict__ w_ih1)
{
    int id = blockIdx.x*512 + threadIdx.x;
#pragma unroll 1
    for (int r = 0; r < 3; r++){
        int id2 = id + r*65536;
        int t = id2 / G3;
        int n = id2 - t*G3;
        float wr[RHYN], wc[CHN];
#pragma unroll
        for (int j = 0; j < RHYN; j++) wr[j] = __ldg(w_ih1 + (size_t)n*273 + MELN + j);
#pragma unroll
        for (int j = 0; j < CHN; j++)
            wc[j] = __ldg(w_ih1 + (size_t)n*273 + MELN + RHYN + 128 + j);
#pragma unroll 1
        for (int b = 0; b < NB; b++){
            float s = g_gi1z[(size_t)b*G3 + n];
            const float* rl = g_rlo + (t*NB + b)*RHYN;
            s += __ldcg(rl)*wr[0] + __ldcg(rl+1)*wr[1] + __ldcg(rl+2)*wr[2];
            const float* c = cond + ((size_t)b*TT + t)*CHN;
#pragma unroll
            for (int j = 0; j < CHN; j++) s += __ldg(c + j)*wc[j];
            g_gi1t[((size_t)t*NB + b)*G3 + n] = s;
        }
    }
}

// ---------------- persistent main kernel ------------------------------------------
__global__ __launch_bounds__(512, 1) void k_main(
    const float* __restrict__ w_ih0, const float* __restrict__ b_hh0,
    const float* __restrict__ w_ih1, const float* __restrict__ b_hh1,
    const float* __restrict__ b_ih2, const float* __restrict__ b_hh2,
    const float* __restrict__ wo0, const float* __restrict__ bo0,
    const float* __restrict__ wo1, const float* __restrict__ bo1,
    const float* __restrict__ cond, float* __restrict__ out)
{
    __shared__ float pool[9216];   // 36 KB: sred / rhy / mel scratch (phase-exclusive)
    int tgt = 0;
    int tid = threadIdx.x, bid = blockIdx.x;
    float acc[2][3][4];

    // ---- rhythm phase ----
#pragma unroll 1
    for (int t = 0; t < TT; t++){
        int cu = t & 1, nx = cu ^ 1;
        gemm_acc(g_Bp0, g_hfrag[cu], acc, pool);
        if (tid < 128)
            epiA(acc, b_hh0, g_gic0, w_ih0, 131, g_ridx + t*NB,
                 g_h + (size_t)cu*NBHd, g_h + (size_t)nx*NBHd, g_hfrag[nx]);
        gbar(tgt);
        if (bid < NB)
            rhy_body(g_h + (size_t)nx*NBHd, wo0, bo0,
                     g_rlo + t*NB*RHYN, g_ridx + (t+1)*NB, pool);
        gbar(tgt);
    }

    // ---- gi1t stage ----
    gi1t_body(cond, w_ih1);
    gbar(tgt);

    // ---- melody phase ----
#pragma unroll 1
    for (int t = 0; t < TT; t++){
        int cu = t & 1, nx = cu ^ 1;
        gemm_acc(g_Bp1, g_hafrag[cu], acc, pool);
        if (tid < 128)
            epiA(acc, b_hh1, g_gi1t + (size_t)t*NB*G3, w_ih1, 273, g_midx + t*NB,
                 g_ha + (size_t)cu*NBHd, g_ha + (size_t)nx*NBHd, g_hafrag[nx]);
        gbar(tgt);

        const uint32_t* fbin = (t == 0) ? g_hafrag[1] : g_hbfrag[cu];
        const float* hbprev = (t == 0) ? (g_ha + (size_t)NBHd) : (g_hb + (size_t)cu*NBHd);
        gemm_acc(g_Bp2h, fbin, acc, pool);
        float gh2[2][3][4];
        if (tid < 128){
#pragma unroll
            for (int n = 0; n < 2; n++)
#pragma unroll
                for (int g = 0; g < 3; g++)
#pragma unroll
                    for (int i = 0; i < 4; i++) gh2[n][g][i] = acc[n][g][i];
        }
        gemm_acc(g_Bp2i, g_hafrag[nx], acc, pool);
        if (tid < 128)
            epi2(acc, gh2, b_ih2, b_hh2, hbprev,
                 g_hb + (size_t)nx*NBHd, g_hbfrag[nx]);
        gbar(tgt);
        if (bid < NB)
            mel_body(g_hb + (size_t)nx*NBHd, wo1, bo1, out, t,
                     g_midx + (t+1)*NB, pool);
        gbar(tgt);
    }
}

// ---------------- host driver ------------------------------------------------------
extern "C" void kernel_launch(void* const* d_in, const int* in_sizes, int n_in,
                              void* d_out, int out_size)
{
    const float* z1    = (const float*)d_in[0];
    const float* z2    = (const float*)d_in[1];
    const float* cond  = (const float*)d_in[2];
    const float* w_ih0 = (const float*)d_in[3];
    const float* w_hh0 = (const float*)d_in[4];
    const float* b_ih0 = (const float*)d_in[5];
    const float* b_hh0 = (const float*)d_in[6];
    const float* w_ih1 = (const float*)d_in[7];
    const float* w_hh1 = (const float*)d_in[8];
    const float* b_ih1 = (const float*)d_in[9];
    const float* b_hh1 = (const float*)d_in[10];
    const float* w_ih2 = (const float*)d_in[11];
    const float* w_hh2 = (const float*)d_in[12];
    const float* b_ih2 = (const float*)d_in[13];
    const float* b_hh2 = (const float*)d_in[14];
    const float* wi0   = (const float*)d_in[15];
    const float* bi0   = (const float*)d_in[16];
    const float* wo0   = (const float*)d_in[17];
    const float* bo0   = (const float*)d_in[18];
    const float* wi1   = (const float*)d_in[19];
    const float* bi1   = (const float*)d_in[20];
    const float* wo1   = (const float*)d_in[21];
    const float* bo1   = (const float*)d_in[22];
    float* out = (float*)d_out;

    float *hB, *haB, *gic0, *gi1z;
    uint32_t *hfr, *hafr;
    cudaGetSymbolAddress((void**)&hB, g_h);
    cudaGetSymbolAddress((void**)&haB, g_ha);
    cudaGetSymbolAddress((void**)&gic0, g_gic0);
    cudaGetSymbolAddress((void**)&gi1z, g_gi1z);
    cudaGetSymbolAddress((void**)&hfr, g_hfrag);
    cudaGetSymbolAddress((void**)&hafr, g_hafrag);

    k_init<<<1, 64>>>();
    k_pack4<<<dim3(BPKSZ/256, 4), 256>>>(w_hh0, w_hh1, w_ih2, w_hh2);

    k_mv<<<dim3(Hd/256, 8), 256>>>(z2, 128, wi0, 128, 0, bi0, Hd, hB, 1);
    k_mv<<<dim3(Hd/256, 8), 256>>>(z1, 128, wi1, 128, 0, bi1, Hd, haB, 1);
    k_mv<<<dim3(G3/256, 8), 256>>>(z2, 128, w_ih0, 131, RHYN, b_ih0, G3, gic0, 0);
    k_mv<<<dim3(G3/256, 8), 256>>>(z1, 128, w_ih1, 273, MELN+RHYN, b_ih1, G3, gi1z, 0);
    k_h2frag<<<64, 256>>>(hB, hfr);
    k_h2frag<<<64, 256>>>(haB, hafr);

    k_main<<<128, 512>>>(w_ih0, b_hh0, w_ih1, b_hh1, b_ih2, b_hh2,
                         wo0, bo0, wo1, bo1, cond, out);
}